// round 9
// baseline (speedup 1.0000x reference)
#include <cuda_runtime.h>
#include <math.h>

#define Bsz 128
#define Tlen 48
#define Dm 512
#define NBLK 128
#define NTHR 512

// ---------------- global scratch ---------------------------------------------
__device__ float g_w[Bsz*Tlen*64];
__device__ unsigned long long g_code[Bsz*Tlen*2];
__device__ int g_src[Bsz*Tlen];
__device__ float g_mem[Bsz*64*Dm];
__device__ float g_read[Bsz*Dm];
__device__ float g_f[Bsz*Dm];
__device__ float g_we[Bsz*Dm];
__device__ float g_ft[Tlen*Bsz*Dm];
__device__ float g_preF[Bsz*Tlen*Dm];     // k_emb @ WfR^T + bf     (rows b*T+t)
__device__ float g_preWE[Bsz*Tlen*Dm];    // y_emb @ WaR^T + ba     (rows b*T+t)
__device__ float g_pre[Tlen*Bsz*2048];    // ft @ Wih^T + bih + bhh (rows t*B+b)
__device__ float g_H[(Tlen+1)*Bsz*Dm];
__device__ float g_C[(Tlen+1)*Bsz*Dm];
// k-major transposed weight slabs (built once per run by stage_wtr)
__device__ float g_WTf[16*512*32];        // [cg][k][n]   Wf left half
__device__ float g_WTa[16*512*32];        // [cg][k][n]   Wa left half
__device__ float g_WTea[16*512*64];       // [cg][k][We n<32 | Wadd n>=32]
__device__ float g_WTh[16*512*128];       // [cg][k][gate*32+n]  Whh
__device__ float g_WTih[32*512*64];       // [cg][k][n]   Wih (2048 cols = 32 cgs)
// tree barrier (monotonic counters -> replay-safe)
__device__ unsigned g_leaf[8];
__device__ unsigned g_root;
__device__ volatile unsigned g_sense;

__device__ __forceinline__ float sigm(float x) { return 1.0f / (1.0f + expf(-x)); }

// ---------------- smem layout (floats) ----------------------------------------
#define OFF_AS   0        // [512][20] seq A tile (par stages reuse: As[64][36]+Ws[32][68])
#define OFF_PART 10240    // split-K partials (max 9216)
#define OFF_G    19456    // 2048: gates / e,a / softmax ivb
#define OFF_WT   21504    // 1024
#define OFF_WN   22528    // 1024
#define OFF_I64  23552    // 64 ints
#define SMEM_FLOATS 23616
#define SMEM_BYTES (SMEM_FLOATS * 4)

// ---------------- grid barrier: tree arrive, release-only fence ---------------
__device__ __forceinline__ void gsync(unsigned& ls) {
    __syncthreads();
    if (threadIdx.x == 0) {
        unsigned target = ls + 1u;
        __threadfence();                                    // release
        unsigned a = atomicAdd(&g_leaf[blockIdx.x & 7u], 1u) + 1u;
        if ((a & 15u) == 0u) {                              // 16 blocks per leaf
            unsigned rt = atomicAdd(&g_root, 1u) + 1u;
            if ((rt & 7u) == 0u) g_sense = target;          // 8 leaves
        }
        while (g_sense != target) { }
        ls = target;
        asm volatile("" ::: "memory");
    }
    __syncthreads();
    // no acquire L1 flush: cross-block data is read via __ldcg (L2-coherent)
}

__device__ __forceinline__ void fma16(float (&acc)[4][4], float4 a, float4 w) {
    acc[0][0]=fmaf(a.x,w.x,acc[0][0]); acc[0][1]=fmaf(a.x,w.y,acc[0][1]);
    acc[0][2]=fmaf(a.x,w.z,acc[0][2]); acc[0][3]=fmaf(a.x,w.w,acc[0][3]);
    acc[1][0]=fmaf(a.y,w.x,acc[1][0]); acc[1][1]=fmaf(a.y,w.y,acc[1][1]);
    acc[1][2]=fmaf(a.y,w.z,acc[1][2]); acc[1][3]=fmaf(a.y,w.w,acc[1][3]);
    acc[2][0]=fmaf(a.z,w.x,acc[2][0]); acc[2][1]=fmaf(a.z,w.y,acc[2][1]);
    acc[2][2]=fmaf(a.z,w.z,acc[2][2]); acc[2][3]=fmaf(a.z,w.w,acc[2][3]);
    acc[3][0]=fmaf(a.w,w.x,acc[3][0]); acc[3][1]=fmaf(a.w,w.y,acc[3][1]);
    acc[3][2]=fmaf(a.w,w.z,acc[3][2]); acc[3][3]=fmaf(a.w,w.w,acc[3][3]);
}

// ---------------- one-time weight transposes ----------------------------------
__device__ void stage_wtr(const float* __restrict__ Wf, const float* __restrict__ Wa,
                          const float* __restrict__ We, const float* __restrict__ Wadd,
                          const float* __restrict__ Whh, const float* __restrict__ Wih)
{
    const int gid = blockIdx.x * NTHR + threadIdx.x;
    const int gs = NBLK * NTHR;                  // 65536
    for (int d = gid; d < 16*512*32; d += gs) {
        int cg = d >> 14, k = (d >> 5) & 511, n = d & 31;
        g_WTf[d] = Wf[(size_t)(cg*32+n)*1024 + k];
        g_WTa[d] = Wa[(size_t)(cg*32+n)*1024 + k];
    }
    for (int d = gid; d < 16*512*64; d += gs) {
        int cg = d >> 15, k = (d >> 6) & 511, n = d & 63;
        g_WTea[d] = (n < 32) ? We[(size_t)(cg*32+n)*512 + k]
                             : Wadd[(size_t)(cg*32+n-32)*512 + k];
    }
    for (int d = gid; d < 16*512*128; d += gs) {
        int cg = d >> 16, k = (d >> 7) & 511, nn = d & 127;
        int gate = nn >> 5, n = nn & 31;
        g_WTh[d] = Whh[(size_t)(gate*512 + cg*32 + n)*512 + k];
    }
    for (int d = gid; d < 32*512*64; d += gs) {
        int cg = d >> 15, k = (d >> 6) & 511, n = d & 63;
        g_WTih[d] = Wih[(size_t)(cg*64+n)*512 + k];
    }
}

// ---------------- parallel GEMMs: preF, preWE, addr (tiles 64x64) -------------
__device__ void stage_par(float* sm, const float* __restrict__ ktab,
                          const float* __restrict__ xtab,
                          const int* __restrict__ q, const int* __restrict__ r,
                          const float* __restrict__ Wf, const float* __restrict__ bf,
                          const float* __restrict__ Wa, const float* __restrict__ ba,
                          const float* __restrict__ Mk)
{
    float* As = sm;                 // [64][36]
    float* Ws = sm + 2304;          // [32][68]
    int* sIdx = (int*)(sm + OFF_I64);
    const int tid = threadIdx.x;
    const int ty = tid >> 3, tx = tid & 7;
    for (int tile = blockIdx.x; tile < 1632; tile += NBLK) {
        int seg, row0, cc0;
        if (tile < 768)       { seg = 0; row0 = (tile >> 3) * 64; cc0 = (tile & 7) * 64; }
        else if (tile < 1536) { int tl = tile - 768;  seg = 1; row0 = (tl >> 3) * 64; cc0 = (tl & 7) * 64; }
        else                  { int tl = tile - 1536; seg = 2; row0 = tl * 64; cc0 = 0; }
        if (tid < 64) {
            int rid = row0 + tid;
            int qi = q[rid];
            sIdx[tid] = (seg == 1) ? (qi + 2000 * r[rid]) : qi;
        }
        __syncthreads();
        float a0=0.f,a1=0.f,a2=0.f,a3=0.f,a4v=0.f,a5=0.f,a6=0.f,a7=0.f;
        for (int ch = 0; ch < 16; ch++) {
            const int kb = ch * 32;
            {   // A tile: 64 rows x 32 k
                int rr = tid >> 3, kq = tid & 7;
                const float* tab = (seg == 1) ? xtab : ktab;
                float4 v = *(const float4*)(tab + (size_t)sIdx[rr] * Dm + kb + kq * 4);
                *(float4*)(As + rr * 36 + kq * 4) = v;
            }
            {   // W tile: 64 cols x 32 k, transposed store
                int n = tid & 63, kq = tid >> 6;
                float4 v;
                if (seg == 0)      v = *(const float4*)(Wf + (size_t)(cc0+n)*1024 + 512 + kb + kq*4);
                else if (seg == 1) v = *(const float4*)(Wa + (size_t)(cc0+n)*1024 + 512 + kb + kq*4);
                else               v = *(const float4*)(Mk + (size_t)(cc0+n)*512 + kb + kq*4);
                float* w = Ws + (kq * 4) * 68 + n;
                w[0] = v.x; w[68] = v.y; w[136] = v.z; w[204] = v.w;
            }
            __syncthreads();
#pragma unroll
            for (int c = 0; c < 32; c++) {
                float a = As[ty * 36 + c];
                float4 w4 = *(const float4*)(Ws + c * 68 + tx * 8);
                float4 w4b = *(const float4*)(Ws + c * 68 + tx * 8 + 4);
                a0 = fmaf(a, w4.x, a0);  a1 = fmaf(a, w4.y, a1);
                a2 = fmaf(a, w4.z, a2);  a3 = fmaf(a, w4.w, a3);
                a4v = fmaf(a, w4b.x, a4v); a5 = fmaf(a, w4b.y, a5);
                a6 = fmaf(a, w4b.z, a6); a7 = fmaf(a, w4b.w, a7);
            }
            __syncthreads();
        }
        const int row = row0 + ty, col = cc0 + tx * 8;
        if (seg == 0) {
            *(float4*)(g_preF + (size_t)row*Dm + col) =
                make_float4(a0+bf[col], a1+bf[col+1], a2+bf[col+2], a3+bf[col+3]);
            *(float4*)(g_preF + (size_t)row*Dm + col + 4) =
                make_float4(a4v+bf[col+4], a5+bf[col+5], a6+bf[col+6], a7+bf[col+7]);
        } else if (seg == 1) {
            *(float4*)(g_preWE + (size_t)row*Dm + col) =
                make_float4(a0+ba[col], a1+ba[col+1], a2+ba[col+2], a3+ba[col+3]);
            *(float4*)(g_preWE + (size_t)row*Dm + col + 4) =
                make_float4(a4v+ba[col+4], a5+ba[col+5], a6+ba[col+6], a7+ba[col+7]);
        } else {
            *(float4*)(g_w + (size_t)row*64 + col) = make_float4(a0, a1, a2, a3);
            *(float4*)(g_w + (size_t)row*64 + col + 4) = make_float4(a4v, a5, a6, a7);
        }
        __syncthreads();
    }
}

// ---------------- softmax + membership codes ----------------------------------
__device__ void stage_softmax(float* sm)
{
    unsigned char* ivb = (unsigned char*)(sm + OFF_G);   // [16][64]
    const int wp = threadIdx.x >> 5, lane = threadIdx.x & 31;
    for (int rr = wp; rr < 48; rr += 16) {
        const int row = blockIdx.x * 48 + rr;
        float v0 = __ldcg(&g_w[row * 64 + lane]);
        float v1 = __ldcg(&g_w[row * 64 + 32 + lane]);
        float mx = fmaxf(v0, v1);
        for (int o = 16; o; o >>= 1) mx = fmaxf(mx, __shfl_xor_sync(0xffffffffu, mx, o));
        float e0 = expf(v0 - mx), e1 = expf(v1 - mx);
        float ss = e0 + e1;
        for (int o = 16; o; o >>= 1) ss += __shfl_xor_sync(0xffffffffu, ss, o);
        float inv = 1.0f / ss;
        float w0 = e0 * inv, w1 = e1 * inv;
        g_w[row * 64 + lane] = w0;
        g_w[row * 64 + 32 + lane] = w1;
        auto ivf = [](float w) -> int {
            float m = fmaxf(fminf((w - 0.075f) / (0.088f - 0.075f),
                                  (1.0f - w) / (1.0f - 0.088f)), 0.0f);
            return (m >= 0.6f) ? 2 : ((m >= 0.1f) ? 1 : 0);
        };
        ivb[wp * 64 + lane] = (unsigned char)ivf(w0);
        ivb[wp * 64 + 32 + lane] = (unsigned char)ivf(w1);
        __syncwarp();
        if (lane == 0) {
            unsigned long long c0 = 0ull, c1 = 0ull;
            for (int i = 0; i < 32; i++) {
                c0 |= (unsigned long long)ivb[wp * 64 + i] << (2 * i);
                c1 |= (unsigned long long)ivb[wp * 64 + 32 + i] << (2 * i);
            }
            g_code[row * 2] = c0;
            g_code[row * 2 + 1] = c1;
        }
        __syncwarp();
    }
}

// ---------------- src scan + g_mem / H0 / C0 / read0 ---------------------------
__device__ void stage_init(float* sm, const float* __restrict__ Mv0,
                           const float* __restrict__ hx0, const float* __restrict__ cx0,
                           int r0, int c0)
{
    float* wT = sm + OFF_WT;
    const int tid = threadIdx.x;
    if (tid < Tlen) {
        const int b = blockIdx.x, i = tid;
        unsigned long long cc0v = __ldcg(&g_code[(b * Tlen + i) * 2]);
        unsigned long long cc1v = __ldcg(&g_code[(b * Tlen + i) * 2 + 1]);
        int sv = i - 1;
        for (int j = i - 1; j >= 0; j--)
            if (__ldcg(&g_code[(b * Tlen + j) * 2]) == cc0v &&
                __ldcg(&g_code[(b * Tlen + j) * 2 + 1]) == cc1v) { sv = j; break; }
        g_src[b * Tlen + i] = sv;
    }
#pragma unroll
    for (int h = 0; h < 2; h++) {
        int i = tid + h * NTHR;
        int bl = i >> 6, m = i & 63;
        wT[i] = __ldcg(&g_w[((r0 + bl) * Tlen) * 64 + m]);
    }
#pragma unroll
    for (int it = 0; it < 64; it++) {
        int i2 = tid + it * NTHR;
        int rr = i2 >> 11, rem = i2 & 2047, m = rem >> 5, cc = rem & 31;
        g_mem[((size_t)(r0 + rr) * 64 + m) * Dm + c0 + cc] = Mv0[m * Dm + c0 + cc];
    }
    __syncthreads();
    {
        int rr = tid >> 5, cc = tid & 31;
        int b = r0 + rr, col = c0 + cc;
        g_H[(size_t)b * Dm + col] = hx0[col];
        g_C[(size_t)b * Dm + col] = cx0[col];
        float racc = 0.f;
#pragma unroll 4
        for (int m = 0; m < 64; m++)
            racc = fmaf(wT[rr * 64 + m], Mv0[m * Dm + col], racc);
        g_read[(size_t)b * Dm + col] = racc;
    }
}

// ---------------- f / we stage: K=512, W direct-LDG from slab ------------------
template<int MODE>   // 0: A=g_read -> tanh(+preF) -> g_f,g_ft ; 1: A=g_f -> (+preWE) -> g_we
__device__ void stage_fwe(float* sm, int t, int r0, int c0)
{
    float* As = sm + OFF_AS;       // [512][20] k-major
    float* part = sm + OFF_PART;   // 16 x [16][36]
    const int tid = threadIdx.x;
    const float* A = (MODE == 0) ? g_read : g_f;
    const float* WT = ((MODE == 0) ? g_WTf : g_WTa) + (size_t)(c0 >> 5) * 16384;
#pragma unroll
    for (int h = 0; h < 4; h++) {
        int i = tid + h * NTHR;
        int rr = i & 15, kq = i >> 4;
        float4 v = __ldcg((const float4*)(A + (size_t)(r0 + rr) * Dm + kq * 4));
        float* a = As + (kq * 4) * 20 + rr;
        a[0] = v.x; a[20] = v.y; a[40] = v.z; a[60] = v.w;
    }
    __syncthreads();
    const int s = tid >> 5, pos = tid & 31, rg = pos >> 3, cg = pos & 7;
    float acc[4][4] = {};
    const int k0 = s * 32;
#pragma unroll 8
    for (int kk = 0; kk < 32; kk++) {
        int k = k0 + kk;
        float4 a4 = *(const float4*)(As + k * 20 + rg * 4);
        float4 w4 = __ldg((const float4*)(WT + k * 32 + cg * 4));
        fma16(acc, a4, w4);
    }
#pragma unroll
    for (int j = 0; j < 4; j++)
        *(float4*)(part + s * 576 + (rg * 4 + j) * 36 + cg * 4) =
            make_float4(acc[j][0], acc[j][1], acc[j][2], acc[j][3]);
    __syncthreads();
    {
        int rr = tid >> 5, cc = tid & 31;
        float v = 0.f;
#pragma unroll
        for (int p = 0; p < 16; p++) v += part[p * 576 + rr * 36 + cc];
        int b = r0 + rr, col = c0 + cc;
        if (MODE == 0) {
            v += __ldcg(&g_preF[((size_t)b * Tlen + t) * Dm + col]);
            v = tanhf(v);
            g_f[(size_t)b * Dm + col] = v;
            g_ft[((size_t)t * Bsz + b) * Dm + col] = v;
        } else {
            v += __ldcg(&g_preWE[((size_t)b * Tlen + t) * Dm + col]);
            g_we[(size_t)b * Dm + col] = v;
        }
    }
}

// ---------------- e/a GEMMs + memory update + fused read_{t+1} -----------------
__device__ void stage_ea(float* sm, const float* __restrict__ be,
                         const float* __restrict__ badd, int t, int r0, int c0)
{
    float* As = sm + OFF_AS;
    float* part = sm + OFF_PART;   // 8 x [16][68]
    float* wT = sm + OFF_WT;
    float* wN = sm + OFF_WN;
    float* EA = sm + OFF_G;        // e [0,512), a [512,1024)
    const int tid = threadIdx.x;
    const float* WT = g_WTea + (size_t)(c0 >> 5) * 32768;
#pragma unroll
    for (int h = 0; h < 2; h++) {
        int i = tid + h * NTHR;
        int bl = i >> 6, m = i & 63;
        wT[i] = __ldcg(&g_w[((r0 + bl) * Tlen + t) * 64 + m]);
        wN[i] = (t + 1 < Tlen) ? __ldcg(&g_w[((r0 + bl) * Tlen + t + 1) * 64 + m]) : 0.0f;
    }
#pragma unroll
    for (int h = 0; h < 4; h++) {
        int i = tid + h * NTHR;
        int rr = i & 15, kq = i >> 4;
        float4 v = __ldcg((const float4*)(g_we + (size_t)(r0 + rr) * Dm + kq * 4));
        float* a = As + (kq * 4) * 20 + rr;
        a[0] = v.x; a[20] = v.y; a[40] = v.z; a[60] = v.w;
    }
    __syncthreads();
    const int s = tid >> 6, pos = tid & 63, rg = pos >> 4, cg = pos & 15;
    float acc[4][4] = {};
    const int k0 = s * 64;
#pragma unroll 8
    for (int kk = 0; kk < 64; kk++) {
        int k = k0 + kk;
        float4 a4 = *(const float4*)(As + k * 20 + rg * 4);
        float4 w4 = __ldg((const float4*)(WT + k * 64 + cg * 4));
        fma16(acc, a4, w4);
    }
#pragma unroll
    for (int j = 0; j < 4; j++)
        *(float4*)(part + s * 1088 + (rg * 4 + j) * 68 + cg * 4) =
            make_float4(acc[j][0], acc[j][1], acc[j][2], acc[j][3]);
    __syncthreads();
#pragma unroll
    for (int h = 0; h < 2; h++) {
        int oid = tid + h * NTHR;
        int rr = oid >> 6, cc = oid & 63;
        float v = 0.f;
#pragma unroll
        for (int p = 0; p < 8; p++) v += part[p * 1088 + rr * 68 + cc];
        if (cc < 32) EA[rr * 32 + cc] = sigm(v + be[c0 + cc]);
        else         EA[512 + rr * 32 + (cc - 32)] = tanhf(v + badd[c0 + cc - 32]);
    }
    __syncthreads();
    {
        int rr = tid >> 5, cc = tid & 31;
        float e = EA[tid], a = EA[512 + tid];
        float racc = 0.f;
        size_t base = ((size_t)(r0 + rr) * 64) * Dm + c0 + cc;
#pragma unroll 4
        for (int m = 0; m < 64; m++) {
            float wt = wT[rr * 64 + m], wn = wN[rr * 64 + m];
            float v = g_mem[base + (size_t)m * Dm];      // block-private slice
            v = v * (1.0f - wt * e) + wt * a;
            g_mem[base + (size_t)m * Dm] = v;
            racc = fmaf(wn, v, racc);
        }
        g_read[(size_t)(r0 + rr) * Dm + c0 + cc] = racc;
    }
}

// ---------------- parallel GEMM: g_pre = ft @ Wih^T + bih + bhh ----------------
__device__ void stage_preG(float* sm, const float* __restrict__ bih,
                           const float* __restrict__ bhh)
{
    float* As = sm;   // [64][36]
    const int tid = threadIdx.x;
    const int ty = tid >> 3, tx = tid & 7;
    for (int tile = blockIdx.x; tile < 3072; tile += NBLK) {
        const int row0 = (tile >> 5) * 64;
        const int cg2 = tile & 31;
        const float* WT = g_WTih + (size_t)cg2 * 32768;
        float a0=0.f,a1=0.f,a2=0.f,a3=0.f,a4v=0.f,a5=0.f,a6=0.f,a7=0.f;
        for (int ch = 0; ch < 16; ch++) {
            const int kb = ch * 32;
            {
                int rr = tid >> 3, kq = tid & 7;
                float4 v = __ldcg((const float4*)(g_ft + (size_t)(row0 + rr) * Dm + kb + kq * 4));
                *(float4*)(As + rr * 36 + kq * 4) = v;
            }
            __syncthreads();
#pragma unroll
            for (int c = 0; c < 32; c++) {
                float a = As[ty * 36 + c];
                float4 w4 = __ldg((const float4*)(WT + (kb + c) * 64 + tx * 8));
                float4 w4b = __ldg((const float4*)(WT + (kb + c) * 64 + tx * 8 + 4));
                a0 = fmaf(a, w4.x, a0);  a1 = fmaf(a, w4.y, a1);
                a2 = fmaf(a, w4.z, a2);  a3 = fmaf(a, w4.w, a3);
                a4v = fmaf(a, w4b.x, a4v); a5 = fmaf(a, w4b.y, a5);
                a6 = fmaf(a, w4b.z, a6); a7 = fmaf(a, w4b.w, a7);
            }
            __syncthreads();
        }
        const int row = row0 + ty, col = cg2 * 64 + tx * 8;
        *(float4*)(g_pre + (size_t)row * 2048 + col) =
            make_float4(a0+bih[col]+bhh[col],     a1+bih[col+1]+bhh[col+1],
                        a2+bih[col+2]+bhh[col+2], a3+bih[col+3]+bhh[col+3]);
        *(float4*)(g_pre + (size_t)row * 2048 + col + 4) =
            make_float4(a4v+bih[col+4]+bhh[col+4], a5+bih[col+5]+bhh[col+5],
                        a6+bih[col+6]+bhh[col+6],  a7+bih[col+7]+bhh[col+7]);
    }
}

// ---------------- hop-LSTM step: gates = h_src @ Whh^T + g_pre -----------------
__device__ void stage_lstm(float* sm, int t, int r0, int c0)
{
    float* As = sm + OFF_AS;
    float* part = sm + OFF_PART;   // 4 x [16][132]
    float* G = sm + OFF_G;         // [16][128]
    int* s16 = (int*)(sm + OFF_I64);
    const int tid = threadIdx.x;
    const float* WT = g_WTh + (size_t)(c0 >> 5) * 65536;
    if (tid < 16) s16[tid] = __ldcg(&g_src[(r0 + tid) * Tlen + t]) + 1;
    __syncthreads();
#pragma unroll
    for (int h = 0; h < 4; h++) {
        int i = tid + h * NTHR;
        int rr = i & 15, kq = i >> 4;
        float4 v = __ldcg((const float4*)(g_H + ((size_t)s16[rr] * Bsz + r0 + rr) * Dm + kq * 4));
        float* a = As + (kq * 4) * 20 + rr;
        a[0] = v.x; a[20] = v.y; a[40] = v.z; a[60] = v.w;
    }
    __syncthreads();
    const int s = tid >> 7, pos = tid & 127, rg = pos >> 5, cg = pos & 31;
    float acc[4][4] = {};
    const int k0 = s * 128;
#pragma unroll 8
    for (int kk = 0; kk < 128; kk++) {
        int k = k0 + kk;
        float4 a4 = *(const float4*)(As + k * 20 + rg * 4);
        float4 w4 = __ldg((const float4*)(WT + k * 128 + cg * 4));
        fma16(acc, a4, w4);
    }
#pragma unroll
    for (int j = 0; j < 4; j++)
        *(float4*)(part + s * 2112 + (rg * 4 + j) * 132 + cg * 4) =
            make_float4(acc[j][0], acc[j][1], acc[j][2], acc[j][3]);
    __syncthreads();
#pragma unroll
    for (int h = 0; h < 4; h++) {
        int oid = tid + h * NTHR;
        int rr = oid >> 7, nn = oid & 127;
        float v = 0.f;
#pragma unroll
        for (int p = 0; p < 4; p++) v += part[p * 2112 + rr * 132 + nn];
        int b = r0 + rr;
        int gate = nn >> 5, col = c0 + (nn & 31);
        v += __ldcg(&g_pre[((size_t)t * Bsz + b) * 2048 + gate * 512 + col]);
        G[rr * 128 + nn] = v;
    }
    __syncthreads();
    {
        int rr = tid >> 5, n = tid & 31;
        int b = r0 + rr, col = c0 + n;
        float gi = G[rr * 128 + n],      gf = G[rr * 128 + 32 + n];
        float gg = G[rr * 128 + 64 + n], go = G[rr * 128 + 96 + n];
        float cin = __ldcg(&g_C[((size_t)s16[rr] * Bsz + b) * Dm + col]);
        float cn = sigm(gf) * cin + sigm(gi) * tanhf(gg);
        float hn = sigm(go) * tanhf(cn);
        g_C[((size_t)(t + 1) * Bsz + b) * Dm + col] = cn;
        g_H[((size_t)(t + 1) * Bsz + b) * Dm + col] = hn;
    }
}

// ---------------- prediction head ----------------------------------------------
__device__ void stage_head(const float* __restrict__ Wp, const float* __restrict__ bp,
                           float* __restrict__ out)
{
    const int wp = threadIdx.x >> 5, lane = threadIdx.x & 31;
    for (int bt = blockIdx.x * 16 + wp; bt < Bsz * Tlen; bt += NBLK * 16) {
        const int b = bt / Tlen, t = bt % Tlen;
        const float* h = &g_H[((size_t)(t + 1) * Bsz + b) * Dm];
        float s = 0.f;
        for (int i = lane; i < Dm; i += 32) s = fmaf(__ldcg(&h[i]), Wp[i], s);
        for (int o = 16; o; o >>= 1) s += __shfl_xor_sync(0xffffffffu, s, o);
        if (lane == 0) out[bt] = sigm(s + bp[0]);
    }
}

// ---------------- the single persistent kernel ---------------------------------
__global__ void __launch_bounds__(NTHR) k_persist(
    const int* __restrict__ q, const int* __restrict__ r,
    const float* __restrict__ Mk, const float* __restrict__ Mv0,
    const float* __restrict__ ktab, const float* __restrict__ xtab,
    const float* __restrict__ We, const float* __restrict__ be,
    const float* __restrict__ Wadd, const float* __restrict__ badd,
    const float* __restrict__ Wa, const float* __restrict__ ba,
    const float* __restrict__ Wf, const float* __restrict__ bf,
    const float* __restrict__ Wih, const float* __restrict__ Whh,
    const float* __restrict__ bih, const float* __restrict__ bhh,
    const float* __restrict__ hx0, const float* __restrict__ cx0,
    const float* __restrict__ Wp, const float* __restrict__ bp,
    float* __restrict__ out)
{
    extern __shared__ float sm[];
    unsigned ls = 0;
    if (threadIdx.x == 0) ls = g_sense;
    const int r0 = (blockIdx.x & 7) * 16;
    const int c0 = (blockIdx.x >> 3) * 32;

    stage_wtr(Wf, Wa, We, Wadd, Whh, Wih);                 gsync(ls);
    stage_par(sm, ktab, xtab, q, r, Wf, bf, Wa, ba, Mk);   gsync(ls);
    stage_softmax(sm);                                     gsync(ls);
    stage_init(sm, Mv0, hx0, cx0, r0, c0);                 gsync(ls);

    for (int t = 0; t < Tlen; t++) {
        stage_fwe<0>(sm, t, r0, c0);                       gsync(ls);
        stage_fwe<1>(sm, t, r0, c0);                       gsync(ls);
        stage_ea(sm, be, badd, t, r0, c0);                 gsync(ls);
    }
    stage_preG(sm, bih, bhh);                              gsync(ls);
    for (int t = 0; t < Tlen; t++) {
        stage_lstm(sm, t, r0, c0);                         gsync(ls);
    }
    stage_head(Wp, bp, out);
}

// ----------------------------------------------------------------------------
extern "C" void kernel_launch(void* const* d_in, const int* in_sizes, int n_in,
                              void* d_out, int out_size)
{
    const int*   q    = (const int*)d_in[0];
    const int*   r    = (const int*)d_in[1];
    const float* Mk   = (const float*)d_in[2];
    const float* Mv0  = (const float*)d_in[3];
    const float* ktab = (const float*)d_in[4];
    const float* xtab = (const float*)d_in[5];
    const float* We   = (const float*)d_in[6];
    const float* be   = (const float*)d_in[7];
    const float* Wadd = (const float*)d_in[8];
    const float* badd = (const float*)d_in[9];
    const float* Wa   = (const float*)d_in[10];
    const float* ba   = (const float*)d_in[11];
    const float* Wf   = (const float*)d_in[12];
    const float* bf   = (const float*)d_in[13];
    const float* Wih  = (const float*)d_in[14];
    const float* Whh  = (const float*)d_in[15];
    const float* bih  = (const float*)d_in[16];
    const float* bhh  = (const float*)d_in[17];
    const float* hx0  = (const float*)d_in[18];
    const float* cx0  = (const float*)d_in[19];
    const float* Wp   = (const float*)d_in[20];
    const float* bp   = (const float*)d_in[21];
    float* out = (float*)d_out;

    static bool attr_set = false;
    if (!attr_set) {
        cudaFuncSetAttribute(k_persist, cudaFuncAttributeMaxDynamicSharedMemorySize, SMEM_BYTES);
        attr_set = true;
    }
    k_persist<<<NBLK, NTHR, SMEM_BYTES>>>(q, r, Mk, Mv0, ktab, xtab, We, be, Wadd, badd,
                                          Wa, ba, Wf, bf, Wih, Whh, bih, bhh,
                                          hx0, cx0, Wp, bp, out);
}

// round 10
// speedup vs baseline: 1.2115x; 1.2115x over previous
#include <cuda_runtime.h>
#include <math.h>

#define Bsz 128
#define Tlen 48
#define Dm 512
#define NBLK 128
#define NTHR 512

// ---------------- global scratch ---------------------------------------------
__device__ float g_w[Bsz*Tlen*64];
__device__ unsigned long long g_code[Bsz*Tlen*2];
__device__ int g_src[Bsz*Tlen];
__device__ float g_read[Bsz*Dm];
__device__ float g_f[Bsz*Dm];
__device__ float g_we[Bsz*Dm];
__device__ float g_ft[Tlen*Bsz*Dm];
__device__ float g_H[(Tlen+1)*Bsz*Dm];
__device__ float g_C[(Tlen+1)*Bsz*Dm];
// barriers: monotonic counters (graph-replay safe). group g uses slot g*32 (128B pad)
__device__ unsigned g_count = 0;
__device__ volatile unsigned g_sense = 0;
__device__ unsigned g_gcnt[8*32];
__device__ volatile unsigned g_gsense[8*32];

__device__ __forceinline__ float sigm(float x) { return 1.0f / (1.0f + expf(-x)); }

// smem layout (floats): [0,32768) memS | [32768,+2560) As | [35328,+4608) Ws
// [39936,+9216) part | [49152,+1024) wT | [50176,+1024) wN | [51200,+16) ints
#define OFF_AS   32768
#define OFF_WS   35328
#define OFF_PART 39936
#define OFF_WT   49152
#define OFF_WN   50176
#define OFF_I16  51200
#define SMEM_FLOATS 51232
#define SMEM_BYTES (SMEM_FLOATS * 4)

// ---------------- global grid barrier (monotonic, 5 uses per launch) ----------
__device__ __forceinline__ void gsync(unsigned& ls) {
    __syncthreads();
    if (threadIdx.x == 0) {
        unsigned target = ls + 1u;
        __threadfence();                              // release
        unsigned a = atomicAdd(&g_count, 1u) + 1u;
        if (a == target * (unsigned)NBLK) g_sense = target;
        while (g_sense != target) { }
        ls = target;
        __threadfence();                              // acquire (L1 flush)
    }
    __syncthreads();
}

// ---------------- group barrier: 16 blocks sharing one row-group --------------
__device__ __forceinline__ void gsync_grp(unsigned& ls, int grp32) {
    __syncthreads();
    if (threadIdx.x == 0) {
        unsigned target = ls + 1u;
        __threadfence();                              // release
        unsigned a = atomicAdd(&g_gcnt[grp32], 1u) + 1u;
        if (a == target * 16u) g_gsense[grp32] = target;
        while (g_gsense[grp32] != target) { }
        ls = target;
        __threadfence();                              // acquire (L1 flush)
    }
    __syncthreads();
}

__device__ __forceinline__ void fma16(float (&acc)[4][4], float4 a, float4 w) {
    acc[0][0]=fmaf(a.x,w.x,acc[0][0]); acc[0][1]=fmaf(a.x,w.y,acc[0][1]);
    acc[0][2]=fmaf(a.x,w.z,acc[0][2]); acc[0][3]=fmaf(a.x,w.w,acc[0][3]);
    acc[1][0]=fmaf(a.y,w.x,acc[1][0]); acc[1][1]=fmaf(a.y,w.y,acc[1][1]);
    acc[1][2]=fmaf(a.y,w.z,acc[1][2]); acc[1][3]=fmaf(a.y,w.w,acc[1][3]);
    acc[2][0]=fmaf(a.z,w.x,acc[2][0]); acc[2][1]=fmaf(a.z,w.y,acc[2][1]);
    acc[2][2]=fmaf(a.z,w.z,acc[2][2]); acc[2][3]=fmaf(a.z,w.w,acc[2][3]);
    acc[3][0]=fmaf(a.w,w.x,acc[3][0]); acc[3][1]=fmaf(a.w,w.y,acc[3][1]);
    acc[3][2]=fmaf(a.w,w.z,acc[3][2]); acc[3][3]=fmaf(a.w,w.w,acc[3][3]);
}

// ---------------- addressing GEMM: g_w[6144,64] = ktab[q] @ Mk^T -------------
__device__ void stage_addr(float* sm, const float* __restrict__ Mk,
                           const float* __restrict__ ktab, const int* __restrict__ q)
{
    float* As = sm + OFF_AS;      // [32][68]
    float* Ws = sm + OFF_WS;      // [32][36]
    float* part = sm + OFF_PART;  // [4][64][36]
    const int tid = threadIdx.x;
    const int s = tid >> 7, pos = tid & 127, rg = pos >> 3, cg = pos & 7;
    for (int tile = blockIdx.x; tile < 192; tile += NBLK) {
        const int row0 = (tile >> 1) * 64, cc0 = (tile & 1) * 32;
        float acc[4][4] = {};
#pragma unroll 1
        for (int ch = 0; ch < 16; ch++) {
            const int kb = ch * 32;
            {
                int rr = tid >> 3, kq = tid & 7;
                int qi = q[row0 + rr];
                float4 v = *(const float4*)(ktab + (size_t)qi * Dm + kb + kq * 4);
                float* a = As + (kq * 4) * 68 + rr;
                a[0] = v.x; a[68] = v.y; a[136] = v.z; a[204] = v.w;
            }
            if (tid < 256) {
                int n = tid >> 3, kq = tid & 7;
                float4 v = *(const float4*)(Mk + (size_t)(cc0 + n) * Dm + kb + kq * 4);
                float* w = Ws + (kq * 4) * 36 + n;
                w[0] = v.x; w[36] = v.y; w[72] = v.z; w[108] = v.w;
            }
            __syncthreads();
#pragma unroll
            for (int kk = 0; kk < 8; kk++) {
                int k = s * 8 + kk;
                float4 a4 = *(const float4*)(As + k * 68 + rg * 4);
                float4 w4 = *(const float4*)(Ws + k * 36 + cg * 4);
                fma16(acc, a4, w4);
            }
            __syncthreads();
        }
#pragma unroll
        for (int j = 0; j < 4; j++)
            *(float4*)(part + s * 2304 + (rg * 4 + j) * 36 + cg * 4) =
                make_float4(acc[j][0], acc[j][1], acc[j][2], acc[j][3]);
        __syncthreads();
        {
            int rr = tid >> 3, cgx = tid & 7;
            float4 v = make_float4(0.f, 0.f, 0.f, 0.f);
#pragma unroll
            for (int p = 0; p < 4; p++) {
                float4 u = *(const float4*)(part + p * 2304 + rr * 36 + cgx * 4);
                v.x += u.x; v.y += u.y; v.z += u.z; v.w += u.w;
            }
            *(float4*)(g_w + (size_t)(row0 + rr) * 64 + cc0 + cgx * 4) = v;
        }
        __syncthreads();
    }
}

// ---------------- softmax + triangular membership codes ----------------------
__device__ void stage_softmax(float* sm)
{
    unsigned char* ivb = (unsigned char*)(sm + OFF_WT);  // [16][64]
    const int wp = threadIdx.x >> 5, lane = threadIdx.x & 31;
    for (int rr = wp; rr < 48; rr += 16) {
        const int row = blockIdx.x * 48 + rr;
        float v0 = g_w[row * 64 + lane];
        float v1 = g_w[row * 64 + 32 + lane];
        float mx = fmaxf(v0, v1);
        for (int o = 16; o; o >>= 1) mx = fmaxf(mx, __shfl_xor_sync(0xffffffffu, mx, o));
        float e0 = expf(v0 - mx), e1 = expf(v1 - mx);
        float ss = e0 + e1;
        for (int o = 16; o; o >>= 1) ss += __shfl_xor_sync(0xffffffffu, ss, o);
        float inv = 1.0f / ss;
        float w0 = e0 * inv, w1 = e1 * inv;
        g_w[row * 64 + lane] = w0;
        g_w[row * 64 + 32 + lane] = w1;
        auto ivf = [](float w) -> int {
            float m = fmaxf(fminf((w - 0.075f) / (0.088f - 0.075f),
                                  (1.0f - w) / (1.0f - 0.088f)), 0.0f);
            return (m >= 0.6f) ? 2 : ((m >= 0.1f) ? 1 : 0);
        };
        ivb[wp * 64 + lane] = (unsigned char)ivf(w0);
        ivb[wp * 64 + 32 + lane] = (unsigned char)ivf(w1);
        __syncwarp();
        if (lane == 0) {
            unsigned long long c0 = 0ull, c1 = 0ull;
            for (int i = 0; i < 32; i++) {
                c0 |= (unsigned long long)ivb[wp * 64 + i] << (2 * i);
                c1 |= (unsigned long long)ivb[wp * 64 + 32 + i] << (2 * i);
            }
            g_code[row * 2] = c0;
            g_code[row * 2 + 1] = c1;
        }
        __syncwarp();
    }
}

// ---------------- src scan + memS / H0 / C0 / read_0 init --------------------
__device__ void stage_init(float* sm, const float* __restrict__ Mv0,
                           const float* __restrict__ hx0, const float* __restrict__ cx0,
                           int r0, int c0)
{
    float* memS = sm;
    float* wT = sm + OFF_WT;
    const int tid = threadIdx.x;
    if (tid < Tlen) {
        const int b = blockIdx.x, i = tid;
        unsigned long long cc0 = g_code[(b * Tlen + i) * 2];
        unsigned long long cc1 = g_code[(b * Tlen + i) * 2 + 1];
        int sv = i - 1;
        for (int j = i - 1; j >= 0; j--)
            if (g_code[(b * Tlen + j) * 2] == cc0 && g_code[(b * Tlen + j) * 2 + 1] == cc1) { sv = j; break; }
        g_src[b * Tlen + i] = sv;
    }
    for (int i = tid; i < 32768; i += NTHR) {
        int m = (i >> 5) & 63, cc = i & 31;
        memS[i] = Mv0[m * Dm + c0 + cc];
    }
    for (int i = tid; i < 1024; i += NTHR) {
        int bl = i >> 6, m = i & 63;
        wT[i] = g_w[((r0 + bl) * Tlen) * 64 + m];
    }
    __syncthreads();
    const int rr = tid >> 5, cc = tid & 31;
    const int b = r0 + rr, col = c0 + cc;
    g_H[(size_t)b * Dm + col] = hx0[col];
    g_C[(size_t)b * Dm + col] = cx0[col];
    float racc = 0.f;
#pragma unroll 4
    for (int m = 0; m < 64; m++)
        racc = fmaf(wT[rr * 64 + m], memS[(rr * 64 + m) * 32 + cc], racc);
    g_read[(size_t)b * Dm + col] = racc;
}

// ---------------- f / we GEMM (K=1024, 4x4 micro, 16-way split-K) ------------
template<int MODE>   // 0: f = tanh(.), X=g_read, tab=ktab ; 1: we = raw, X=g_f, tab=xtab
__device__ void stage_fwe(float* sm, const float* __restrict__ W, const float* __restrict__ bias,
                          const float* __restrict__ tab, const int* __restrict__ q,
                          const int* __restrict__ r, int t, int r0, int c0)
{
    float* As = sm + OFF_AS;      // per group g: [32][20] at g*640
    float* Ws = sm + OFF_WS;      // per group g: [32][36] at g*1152
    float* part = sm + OFF_PART;  // [16][16][36]
    int* sQ = (int*)(sm + OFF_I16);
    const int tid = threadIdx.x;
    const int g = tid >> 7, gt = tid & 127;
    const int s = gt >> 5, pos = gt & 31, rg = pos >> 3, cg = pos & 7;
    if (tid < 16) {
        int b = r0 + tid;
        int qi = q[b * Tlen + t];
        sQ[tid] = (MODE == 0) ? qi : (qi + 2000 * r[b * Tlen + t]);
    }
    __syncthreads();
    const float* X = (MODE == 0) ? g_read : g_f;
    float acc[4][4] = {};
#pragma unroll 1
    for (int ch = 0; ch < 8; ch++) {
        const int kb = g * 256 + ch * 32;
        {
            int rr = gt >> 3, kq = gt & 7;
            const float* srcp = (g < 2)
                ? X + (size_t)(r0 + rr) * Dm + kb + kq * 4
                : tab + (size_t)sQ[rr] * Dm + (kb - Dm) + kq * 4;
            float4 v = *(const float4*)srcp;
            float* a = As + g * 640 + (kq * 4) * 20 + rr;
            a[0] = v.x; a[20] = v.y; a[40] = v.z; a[60] = v.w;
        }
#pragma unroll
        for (int h = 0; h < 2; h++) {
            int i2 = gt * 2 + h;
            int n = i2 >> 3, kq = i2 & 7;
            float4 v = *(const float4*)(W + (size_t)(c0 + n) * 1024 + kb + kq * 4);
            float* w = Ws + g * 1152 + (kq * 4) * 36 + n;
            w[0] = v.x; w[36] = v.y; w[72] = v.z; w[108] = v.w;
        }
        __syncthreads();
#pragma unroll
        for (int kk = 0; kk < 8; kk++) {
            int k = s * 8 + kk;
            float4 a4 = *(const float4*)(As + g * 640 + k * 20 + rg * 4);
            float4 w4 = *(const float4*)(Ws + g * 1152 + k * 36 + cg * 4);
            fma16(acc, a4, w4);
        }
        __syncthreads();
    }
    const int sid = g * 4 + s;
#pragma unroll
    for (int j = 0; j < 4; j++)
        *(float4*)(part + sid * 576 + (rg * 4 + j) * 36 + cg * 4) =
            make_float4(acc[j][0], acc[j][1], acc[j][2], acc[j][3]);
    __syncthreads();
    {
        const int rr = tid >> 5, cc = tid & 31;
        float v = 0.f;
#pragma unroll
        for (int p = 0; p < 16; p++) v += part[p * 576 + rr * 36 + cc];
        v += bias[c0 + cc];
        const int b = r0 + rr;
        if (MODE == 0) {
            v = tanhf(v);
            g_f[(size_t)b * Dm + c0 + cc] = v;
            g_ft[((size_t)t * Bsz + b) * Dm + c0 + cc] = v;
        } else {
            g_we[(size_t)b * Dm + c0 + cc] = v;
        }
    }
}

// ---------------- e/a GEMMs + smem-resident memory update + read_{t+1} -------
__device__ void stage_ea(float* sm, const float* __restrict__ We, const float* __restrict__ be,
                         const float* __restrict__ Wa, const float* __restrict__ ba,
                         int t, int r0, int c0)
{
    float* memS = sm;
    float* As = sm + OFF_AS;
    float* Ws = sm + OFF_WS;
    float* part = sm + OFF_PART;
    float* wT = sm + OFF_WT;
    float* wN = sm + OFF_WN;
    const int tid = threadIdx.x;
    const int g = tid >> 7, gt = tid & 127;
    const int s = gt >> 5, pos = gt & 31, rg = pos >> 3, cg = pos & 7;
    for (int i = tid; i < 1024; i += NTHR) {
        int bl = i >> 6, m = i & 63;
        wT[i] = g_w[((r0 + bl) * Tlen + t) * 64 + m];
        wN[i] = (t + 1 < Tlen) ? g_w[((r0 + bl) * Tlen + t + 1) * 64 + m] : 0.0f;
    }
    const float* W = (g < 2) ? We : Wa;
    float acc[4][4] = {};
#pragma unroll 1
    for (int ch = 0; ch < 8; ch++) {
        const int kb = (g & 1) * 256 + ch * 32;
        {
            int rr = gt >> 3, kq = gt & 7;
            float4 v = *(const float4*)(g_we + (size_t)(r0 + rr) * Dm + kb + kq * 4);
            float* a = As + g * 640 + (kq * 4) * 20 + rr;
            a[0] = v.x; a[20] = v.y; a[40] = v.z; a[60] = v.w;
        }
#pragma unroll
        for (int h = 0; h < 2; h++) {
            int i2 = gt * 2 + h;
            int n = i2 >> 3, kq = i2 & 7;
            float4 v = *(const float4*)(W + (size_t)(c0 + n) * Dm + kb + kq * 4);
            float* w = Ws + g * 1152 + (kq * 4) * 36 + n;
            w[0] = v.x; w[36] = v.y; w[72] = v.z; w[108] = v.w;
        }
        __syncthreads();
#pragma unroll
        for (int kk = 0; kk < 8; kk++) {
            int k = s * 8 + kk;
            float4 a4 = *(const float4*)(As + g * 640 + k * 20 + rg * 4);
            float4 w4 = *(const float4*)(Ws + g * 1152 + k * 36 + cg * 4);
            fma16(acc, a4, w4);
        }
        __syncthreads();
    }
    const int sid = g * 4 + s;
#pragma unroll
    for (int j = 0; j < 4; j++)
        *(float4*)(part + sid * 576 + (rg * 4 + j) * 36 + cg * 4) =
            make_float4(acc[j][0], acc[j][1], acc[j][2], acc[j][3]);
    __syncthreads();
    {
        const int rr = tid >> 5, cc = tid & 31;
        float ve = 0.f, va = 0.f;
#pragma unroll
        for (int p = 0; p < 8; p++)  ve += part[p * 576 + rr * 36 + cc];
#pragma unroll
        for (int p = 8; p < 16; p++) va += part[p * 576 + rr * 36 + cc];
        ve = sigm(ve + be[c0 + cc]);
        va = tanhf(va + ba[c0 + cc]);
        float racc = 0.f;
#pragma unroll 4
        for (int m = 0; m < 64; m++) {
            float wt = wT[rr * 64 + m], wn = wN[rr * 64 + m];
            float* p = &memS[(rr * 64 + m) * 32 + cc];
            float v = *p;
            v = v * (1.0f - wt * ve) + wt * va;
            *p = v;
            racc = fmaf(wn, v, racc);
        }
        g_read[(size_t)(r0 + rr) * Dm + c0 + cc] = racc;
    }
}

// ---------------- hop-LSTM step: [f_t | h_src] @ [Wih|Whh]^T, K=1024 ---------
__device__ void stage_lstm(float* sm, const float* __restrict__ Wih, const float* __restrict__ Whh,
                           const float* __restrict__ bih, const float* __restrict__ bhh,
                           int t, int r0, int c0)
{
    float* As = sm + OFF_AS;      // shared [32][20]
    float* Ws = sm + OFF_WS;
    float* part = sm + OFF_PART;
    int* s16 = (int*)(sm + OFF_I16);
    const int tid = threadIdx.x;
    const int g = tid >> 7, gt = tid & 127;
    const int s = gt >> 5, pos = gt & 31, rg = pos >> 3, cg = pos & 7;
    if (tid < 16) s16[tid] = g_src[(r0 + tid) * Tlen + t] + 1;
    __syncthreads();
    float acc[4][4] = {};
#pragma unroll 1
    for (int ch = 0; ch < 32; ch++) {
        const int kb = ch * 32;
        if (g == 0) {
            int rr = gt >> 3, kq = gt & 7;
            const float* srcp = (kb < Dm)
                ? g_ft + ((size_t)t * Bsz + r0 + rr) * Dm + kb + kq * 4
                : g_H + ((size_t)s16[rr] * Bsz + r0 + rr) * Dm + (kb - Dm) + kq * 4;
            float4 v = *(const float4*)srcp;
            float* a = As + (kq * 4) * 20 + rr;
            a[0] = v.x; a[20] = v.y; a[40] = v.z; a[60] = v.w;
        }
#pragma unroll
        for (int h = 0; h < 2; h++) {
            int i2 = gt * 2 + h;
            int n = i2 >> 3, kq = i2 & 7;
            const float* wsrc = (kb < Dm)
                ? Wih + (size_t)(g * Dm + c0 + n) * Dm + kb + kq * 4
                : Whh + (size_t)(g * Dm + c0 + n) * Dm + (kb - Dm) + kq * 4;
            float4 v = *(const float4*)wsrc;
            float* w = Ws + g * 1152 + (kq * 4) * 36 + n;
            w[0] = v.x; w[36] = v.y; w[72] = v.z; w[108] = v.w;
        }
        __syncthreads();
#pragma unroll
        for (int kk = 0; kk < 8; kk++) {
            int k = s * 8 + kk;
            float4 a4 = *(const float4*)(As + k * 20 + rg * 4);
            float4 w4 = *(const float4*)(Ws + g * 1152 + k * 36 + cg * 4);
            fma16(acc, a4, w4);
        }
        __syncthreads();
    }
    const int sid = g * 4 + s;
#pragma unroll
    for (int j = 0; j < 4; j++)
        *(float4*)(part + sid * 576 + (rg * 4 + j) * 36 + cg * 4) =
            make_float4(acc[j][0], acc[j][1], acc[j][2], acc[j][3]);
    __syncthreads();
    {
        const int rr = tid >> 5, cc = tid & 31;
        float gi = 0.f, gf = 0.f, gg = 0.f, go = 0.f;
#pragma unroll
        for (int p = 0; p < 4; p++)   gi += part[p * 576 + rr * 36 + cc];
#pragma unroll
        for (int p = 4; p < 8; p++)   gf += part[p * 576 + rr * 36 + cc];
#pragma unroll
        for (int p = 8; p < 12; p++)  gg += part[p * 576 + rr * 36 + cc];
#pragma unroll
        for (int p = 12; p < 16; p++) go += part[p * 576 + rr * 36 + cc];
        const int b = r0 + rr, col = c0 + cc;
        gi += bih[col] + bhh[col];
        gf += bih[512 + col] + bhh[512 + col];
        gg += bih[1024 + col] + bhh[1024 + col];
        go += bih[1536 + col] + bhh[1536 + col];
        float cin = g_C[((size_t)s16[rr] * Bsz + b) * Dm + col];
        float cn = sigm(gf) * cin + sigm(gi) * tanhf(gg);
        float hn = sigm(go) * tanhf(cn);
        g_C[((size_t)(t + 1) * Bsz + b) * Dm + col] = cn;
        g_H[((size_t)(t + 1) * Bsz + b) * Dm + col] = hn;
    }
}

// ---------------- prediction head --------------------------------------------
__device__ void stage_head(const float* __restrict__ Wp, const float* __restrict__ bp,
                           float* __restrict__ out)
{
    const int wp = threadIdx.x >> 5, lane = threadIdx.x & 31;
    for (int bt = blockIdx.x * 16 + wp; bt < Bsz * Tlen; bt += NBLK * 16) {
        const int b = bt / Tlen, t = bt % Tlen;
        const float* h = &g_H[((size_t)(t + 1) * Bsz + b) * Dm];
        float s = 0.f;
        for (int i = lane; i < Dm; i += 32) s = fmaf(h[i], Wp[i], s);
        for (int o = 16; o; o >>= 1) s += __shfl_xor_sync(0xffffffffu, s, o);
        if (lane == 0) out[bt] = sigm(s + bp[0]);
    }
}

// ---------------- the single persistent kernel -------------------------------
__global__ void __launch_bounds__(NTHR, 1) k_persist(
    const int* __restrict__ q, const int* __restrict__ r,
    const float* __restrict__ Mk, const float* __restrict__ Mv0,
    const float* __restrict__ ktab, const float* __restrict__ xtab,
    const float* __restrict__ We, const float* __restrict__ be,
    const float* __restrict__ Wadd, const float* __restrict__ badd,
    const float* __restrict__ Wa, const float* __restrict__ ba,
    const float* __restrict__ Wf, const float* __restrict__ bf,
    const float* __restrict__ Wih, const float* __restrict__ Whh,
    const float* __restrict__ bih, const float* __restrict__ bhh,
    const float* __restrict__ hx0, const float* __restrict__ cx0,
    const float* __restrict__ Wp, const float* __restrict__ bp,
    float* __restrict__ out)
{
    extern __shared__ float sm[];
    const int grp = blockIdx.x & 7;
    const int grp32 = grp * 32;
    unsigned ls = 0, lsr = 0;
    if (threadIdx.x == 0) { ls = g_sense; lsr = g_gsense[grp32]; }
    const int r0 = grp * 16;
    const int c0 = (blockIdx.x >> 3) * 32;

    stage_addr(sm, Mk, ktab, q);                          gsync(ls);
    stage_softmax(sm);                                    gsync(ls);
    stage_init(sm, Mv0, hx0, cx0, r0, c0);                gsync(ls);

    // sequential region: only the 16 blocks sharing r0 exchange data -> group syncs
    for (int t = 0; t < Tlen; t++) {
        stage_fwe<0>(sm, Wf, bf, ktab, q, r, t, r0, c0);  gsync_grp(lsr, grp32);
        stage_fwe<1>(sm, Wa, ba, xtab, q, r, t, r0, c0);  gsync_grp(lsr, grp32);
        stage_ea(sm, We, be, Wadd, badd, t, r0, c0);      gsync_grp(lsr, grp32);
    }
    for (int t = 0; t < Tlen; t++) {
        stage_lstm(sm, Wih, Whh, bih, bhh, t, r0, c0);    gsync_grp(lsr, grp32);
    }
    gsync(ls);                                            // head reads all rows
    stage_head(Wp, bp, out);
}

// ----------------------------------------------------------------------------
extern "C" void kernel_launch(void* const* d_in, const int* in_sizes, int n_in,
                              void* d_out, int out_size)
{
    const int*   q    = (const int*)d_in[0];
    const int*   r    = (const int*)d_in[1];
    const float* Mk   = (const float*)d_in[2];
    const float* Mv0  = (const float*)d_in[3];
    const float* ktab = (const float*)d_in[4];
    const float* xtab = (const float*)d_in[5];
    const float* We   = (const float*)d_in[6];
    const float* be   = (const float*)d_in[7];
    const float* Wadd = (const float*)d_in[8];
    const float* badd = (const float*)d_in[9];
    const float* Wa   = (const float*)d_in[10];
    const float* ba   = (const float*)d_in[11];
    const float* Wf   = (const float*)d_in[12];
    const float* bf   = (const float*)d_in[13];
    const float* Wih  = (const float*)d_in[14];
    const float* Whh  = (const float*)d_in[15];
    const float* bih  = (const float*)d_in[16];
    const float* bhh  = (const float*)d_in[17];
    const float* hx0  = (const float*)d_in[18];
    const float* cx0  = (const float*)d_in[19];
    const float* Wp   = (const float*)d_in[20];
    const float* bp   = (const float*)d_in[21];
    float* out = (float*)d_out;

    static bool attr_set = false;
    if (!attr_set) {
        cudaFuncSetAttribute(k_persist, cudaFuncAttributeMaxDynamicSharedMemorySize, SMEM_BYTES);
        attr_set = true;
    }
    k_persist<<<NBLK, NTHR, SMEM_BYTES>>>(q, r, Mk, Mv0, ktab, xtab, We, be, Wadd, badd,
                                          Wa, ba, Wf, bf, Wih, Whh, bih, bhh,
                                          hx0, cx0, Wp, bp, out);
}